// round 11
// baseline (speedup 1.0000x reference)
#include <cuda_runtime.h>
#include <cstdint>

#define NROW 8192
#define LATENT 128
#define HID 32
#define MSG 64
#define THRESH 1.5f

#define NCB 16                // column blocks (confirmed optimal R10)
#define COLB (NROW / NCB)     // 512 cols per CTA
#define CTILE 128             // cols per smem tile
#define NT (COLB / CTILE)     // 4 tiles
#define TPB2 512

// ---------------- device scratch (no allocation allowed) -------------------
__device__ __align__(16) float g_h[NROW * HID];          // 1 MB
__device__ __align__(16) float g_msgF[NROW * MSG];       // 2 MB row-major
__device__ __align__(16) float g_part[NCB * NROW * MSG]; // 32 MB fail-sum partials
__device__ float g_S[MSG];                               // column sums of messages

// ---------------- asm helpers -----------------------------------------------
__device__ __forceinline__ uint32_t smem_u32(const void* p) {
    uint32_t a;
    asm("{ .reg .u64 t; cvta.to.shared.u64 t, %1; cvt.u32.u64 %0, t; }" : "=r"(a) : "l"(p));
    return a;
}
#define CP_ASYNC16(sm, gp) \
    asm volatile("cp.async.cg.shared.global [%0], [%1], 16;" :: "r"(sm), "l"(gp) : "memory")
#define CP_COMMIT() asm volatile("cp.async.commit_group;" ::: "memory")
#define CP_WAIT0()  asm volatile("cp.async.wait_group 0;" ::: "memory")

// packed fp32x2 add (Blackwell): acc += v in one instruction
__device__ __forceinline__ void fadd2(uint64_t& a, uint64_t v) {
    asm("add.rn.f32x2 %0, %0, %1;" : "+l"(a) : "l"(v));
}

// ---------------- threefry / gumbel ----------------------------------------
__device__ __forceinline__ uint32_t rotl32(uint32_t x, int r) { return __funnelshift_l(x, x, r); }
__device__ __forceinline__ void threefry2x32_042(uint32_t x0, uint32_t x1,
                                                 uint32_t& o0, uint32_t& o1) {
    const uint32_t k0 = 0u, k1 = 42u, k2 = 0u ^ 42u ^ 0x1BD11BDAu;
    x0 += k0; x1 += k1;
#define TF_RND(r) { x0 += x1; x1 = rotl32(x1, r); x1 ^= x0; }
    TF_RND(13) TF_RND(15) TF_RND(26) TF_RND(6)
    x0 += k1; x1 += k2 + 1u;
    TF_RND(17) TF_RND(29) TF_RND(16) TF_RND(24)
    x0 += k2; x1 += k0 + 2u;
    TF_RND(13) TF_RND(15) TF_RND(26) TF_RND(6)
    x0 += k0; x1 += k1 + 3u;
    TF_RND(17) TF_RND(29) TF_RND(16) TF_RND(24)
    x0 += k1; x1 += k2 + 4u;
    TF_RND(13) TF_RND(15) TF_RND(26) TF_RND(6)
    x0 += k2; x1 += k0 + 5u;
#undef TF_RND
    o0 = x0; o1 = x1;
}
__device__ __forceinline__ float gumbel_at(uint32_t i) {
    uint32_t o0, o1;
    threefry2x32_042(0u, i, o0, o1);
    const uint32_t bits = o0 ^ o1;
    float u = __uint_as_float((bits >> 9) | 0x3f800000u) - 1.0f;
    u = u * (1.0f - 1e-10f) + 1e-10f;
    u = fmaxf(1e-10f, u);
    return -__logf(-__logf(u));
}

// ---------------- K1: 16 rows/CTA, 2 rows/thread, shared weight loads -------
__global__ __launch_bounds__(256) void k1_enc(
    const float* __restrict__ z,
    const float* __restrict__ encW, const float* __restrict__ encb,
    const float* __restrict__ msgW, const float* __restrict__ msgb)
{
    __shared__ float  z_s[16 * LATENT];   // 8 KB
    __shared__ float  h_s[16 * HID];      // 2 KB
    __shared__ float2 m_s[16 * 32];       // 4 KB

    const int t  = threadIdx.x;
    const int i0 = blockIdx.x * 16;

    // load 16 rows of z: 2048 floats = 512 float4, 2 per thread
    {
        const float4* src = reinterpret_cast<const float4*>(z + (size_t)i0 * LATENT);
        float4* dst = reinterpret_cast<float4*>(z_s);
        dst[t]       = src[t];
        dst[t + 256] = src[t + 256];
    }
    __syncthreads();

    const int w = t >> 5, c = t & 31;
    const int r0 = w * 2, r1 = r0 + 1;

    // 4 independent chains; each encW load feeds 2 rows
    float a00 = encb[c], a01 = 0.0f, a10 = a00, a11 = 0.0f;
    const float* z0 = z_s + r0 * LATENT;
    const float* z1 = z_s + r1 * LATENT;
#pragma unroll
    for (int k = 0; k < LATENT; k += 2) {
        const float w0 = encW[(k + 0) * HID + c];
        const float w1 = encW[(k + 1) * HID + c];
        a00 = fmaf(z0[k + 0], w0, a00);
        a01 = fmaf(z0[k + 1], w1, a01);
        a10 = fmaf(z1[k + 0], w0, a10);
        a11 = fmaf(z1[k + 1], w1, a11);
    }
    const float h0 = fmaxf(a00 + a01, 0.0f);
    const float h1 = fmaxf(a10 + a11, 0.0f);
    h_s[r0 * HID + c] = h0;
    h_s[r1 * HID + c] = h1;
    g_h[(size_t)(i0 + r0) * HID + c] = h0;
    g_h[(size_t)(i0 + r1) * HID + c] = h1;
    __syncthreads();

    // msg: each msgW float2 load feeds 2 rows (4 FMAs)
    float2 m0 = make_float2(msgb[2 * c], msgb[2 * c + 1]);
    float2 m1 = m0;
#pragma unroll
    for (int k = 0; k < HID; ++k) {
        const float hk0 = h_s[r0 * HID + k];
        const float hk1 = h_s[r1 * HID + k];
        const float2 wv = reinterpret_cast<const float2*>(msgW)[k * 32 + c];
        m0.x = fmaf(hk0, wv.x, m0.x);
        m0.y = fmaf(hk0, wv.y, m0.y);
        m1.x = fmaf(hk1, wv.x, m1.x);
        m1.y = fmaf(hk1, wv.y, m1.y);
    }
    reinterpret_cast<float2*>(g_msgF)[(size_t)(i0 + r0) * 32 + c] = m0;
    reinterpret_cast<float2*>(g_msgF)[(size_t)(i0 + r1) * 32 + c] = m1;
    m_s[r0 * 32 + c] = m0;
    m_s[r1 * 32 + c] = m1;
    __syncthreads();

    if (t < MSG) {
        float s = 0.0f;
#pragma unroll
        for (int rr = 0; rr < 16; ++rr) {
            float2 mm = m_s[rr * 32 + (t >> 1)];
            s += (t & 1) ? mm.y : mm.x;
        }
        atomicAdd(&g_S[t], s);
    }
}

// ---------------- K2: fail-sum partials, 2D grid (rowblk x colblk) ----------
// EXACT R5/R9 hot loop. CTA = 64 rows x 512 cols. 16 warps, 4 rows/warp.
__global__ __launch_bounds__(TPB2, 3) void k2_agg(const float* __restrict__ dists)
{
    extern __shared__ float msg_s[];          // 2 x 128*64 floats = 64KB

    const int tid  = threadIdx.x;
    const int wid  = tid >> 5;
    const int lane = tid & 31;
    const int rb   = blockIdx.x;              // 0..127
    const int cb   = blockIdx.y;              // 0..15
    const int row0 = rb * 64 + wid * 4;
    const int col0 = cb * COLB;

    const float* d0 = dists + (size_t)(row0 + 0) * NROW + col0 + lane * 4;
    const float* d1 = d0 + NROW;
    const float* d2 = d1 + NROW;
    const float* d3 = d2 + NROW;

    uint64_t acc[4] = {0ull, 0ull, 0ull, 0ull};   // packed f32x2 accumulators

    const uint32_t sm0 = smem_u32(msg_s);

    // prefetch tile 0 into buffer 0
    {
        const float4* src = reinterpret_cast<const float4*>(g_msgF + (size_t)col0 * MSG);
#pragma unroll
        for (int q = 0; q < 4; ++q)
            CP_ASYNC16(sm0 + (tid + q * TPB2) * 16, src + tid + q * TPB2);
        CP_COMMIT();
    }

#pragma unroll 1
    for (int t = 0; t < NT; ++t) {
        const int s = t & 1;
        CP_WAIT0();
        __syncthreads();
        if (t + 1 < NT) {
            const uint32_t dst = sm0 + ((s ^ 1) * CTILE * MSG) * 4;
            const float4* src = reinterpret_cast<const float4*>(
                g_msgF + (size_t)(col0 + (t + 1) * CTILE) * MSG);
#pragma unroll
            for (int q = 0; q < 4; ++q)
                CP_ASYNC16(dst + (tid + q * TPB2) * 16, src + tid + q * TPB2);
            CP_COMMIT();
        }

        const char* ms = reinterpret_cast<const char*>(msg_s)
                       + s * (CTILE * MSG * 4) + lane * 8;
        const int ofs = t * CTILE;

        // front-batch all 4 row loads (MLP=4), streaming (evict-first)
        const float4 dA = __ldcs(reinterpret_cast<const float4*>(d0 + ofs));
        const float4 dB = __ldcs(reinterpret_cast<const float4*>(d1 + ofs));
        const float4 dC = __ldcs(reinterpret_cast<const float4*>(d2 + ofs));
        const float4 dD = __ldcs(reinterpret_cast<const float4*>(d3 + ofs));

#define ROW_TILE(r, d4) { \
        unsigned m0 = __ballot_sync(0xffffffffu, d4.x >= THRESH);                     \
        unsigned m1 = __ballot_sync(0xffffffffu, d4.y >= THRESH);                     \
        unsigned m2 = __ballot_sync(0xffffffffu, d4.z >= THRESH);                     \
        unsigned m3 = __ballot_sync(0xffffffffu, d4.w >= THRESH);                     \
        while (m0) { int b = __ffs(m0) - 1; m0 &= m0 - 1;                             \
            fadd2(acc[r], *reinterpret_cast<const uint64_t*>(ms + 0 * 256 + b * 1024)); } \
        while (m1) { int b = __ffs(m1) - 1; m1 &= m1 - 1;                             \
            fadd2(acc[r], *reinterpret_cast<const uint64_t*>(ms + 1 * 256 + b * 1024)); } \
        while (m2) { int b = __ffs(m2) - 1; m2 &= m2 - 1;                             \
            fadd2(acc[r], *reinterpret_cast<const uint64_t*>(ms + 2 * 256 + b * 1024)); } \
        while (m3) { int b = __ffs(m3) - 1; m3 &= m3 - 1;                             \
            fadd2(acc[r], *reinterpret_cast<const uint64_t*>(ms + 3 * 256 + b * 1024)); } }

        ROW_TILE(0, dA)
        ROW_TILE(1, dB)
        ROW_TILE(2, dC)
        ROW_TILE(3, dD)
#undef ROW_TILE
    }

    uint64_t* gp = reinterpret_cast<uint64_t*>(g_part) +
                   ((size_t)cb * NROW + row0) * 32 + lane;
#pragma unroll
    for (int r = 0; r < 4; ++r) gp[r * 32] = acc[r];
}

// ---------------- K3: combine partials + gumbel + fused tail -----------------
// 256 CTAs x 512 thr; 16 warps x 2 interleaved rows (2 independent chains).
__global__ __launch_bounds__(TPB2) void k3_tail(
    const float* __restrict__ dists, const float* __restrict__ tau,
    const float* __restrict__ updW,  const float* __restrict__ updb,
    const float* __restrict__ outW,  const float* __restrict__ outb,
    float* __restrict__ out)
{
    const int wid  = threadIdx.x >> 5;
    const int lane = threadIdx.x & 31;
    const float itau = 1.0f / tau[0];

    const size_t row[2] = { (size_t)blockIdx.x * 32 + wid * 2,
                            (size_t)blockIdx.x * 32 + wid * 2 + 1 };

    const float2 Sv = reinterpret_cast<const float2*>(g_S)[lane];

    float a0[2], a1[2], h_own[2];
#pragma unroll
    for (int j = 0; j < 2; ++j) { a0[j] = Sv.x; a1[j] = Sv.y; }

    // interleaved partial combine (independent loads, MLP high)
#pragma unroll
    for (int p = 0; p < NCB; ++p) {
#pragma unroll
        for (int j = 0; j < 2; ++j) {
            const float2 pv = reinterpret_cast<const float2*>(g_part)
                [((size_t)p * NROW + row[j]) * 32 + lane];
            a0[j] -= pv.x; a1[j] -= pv.y;
        }
    }
#pragma unroll
    for (int j = 0; j < 2; ++j) {
        const float dii = dists[row[j] * NROW + row[j]];
        const float2 mi = reinterpret_cast<const float2*>(g_msgF)[row[j] * 32 + lane];
        const float sub = (dii < THRESH) ? 1.0f : 0.0f;
        a0[j] -= sub * mi.x;
        a1[j] -= sub * mi.y;
        h_own[j] = g_h[row[j] * HID + lane];
    }

    // gumbels (4 threefry evals, independent)
    float gum0[2], gum1[2];
#pragma unroll
    for (int j = 0; j < 2; ++j) {
        const uint32_t gi = (uint32_t)row[j] * 64u + 2u * lane;
        gum0[j] = gumbel_at(gi);
        gum1[j] = gumbel_at(gi + 1);
    }

    float acc2[2] = { updb[lane], updb[lane] };
#pragma unroll
    for (int k = 0; k < 32; ++k) {
        const float wA = updW[k * HID + lane];
        const float wB = updW[(32 + k) * HID + lane];
        const float wC = updW[(64 + k) * HID + lane];
#pragma unroll
        for (int j = 0; j < 2; ++j) {
            const float hk = __shfl_sync(0xffffffffu, h_own[j], k);
            const float src = (k & 1) ? a1[j] : a0[j];
            const float gA = __shfl_sync(0xffffffffu, src, k >> 1);
            const float gB = __shfl_sync(0xffffffffu, src, 16 + (k >> 1));
            acc2[j] = fmaf(hk, wA, acc2[j]);
            acc2[j] = fmaf(gA, wB, acc2[j]);
            acc2[j] = fmaf(gB, wC, acc2[j]);
        }
    }
    float h2v[2] = { fmaxf(acc2[0], 0.0f), fmaxf(acc2[1], 0.0f) };

    float2 lg[2];
#pragma unroll
    for (int j = 0; j < 2; ++j) lg[j] = make_float2(outb[2 * lane], outb[2 * lane + 1]);
#pragma unroll
    for (int k = 0; k < 32; ++k) {
        const float2 w = reinterpret_cast<const float2*>(outW)[k * 32 + lane];
#pragma unroll
        for (int j = 0; j < 2; ++j) {
            const float h2k = __shfl_sync(0xffffffffu, h2v[j], k);
            lg[j].x = fmaf(h2k, w.x, lg[j].x);
            lg[j].y = fmaf(h2k, w.y, lg[j].y);
        }
    }

#pragma unroll
    for (int j = 0; j < 2; ++j) {
        const float v0 = (lg[j].x + gum0[j]) * itau;
        const float v1 = (lg[j].y + gum1[j]) * itau;

        float mx = fmaxf(v0, v1);
#pragma unroll
        for (int o = 16; o; o >>= 1) mx = fmaxf(mx, __shfl_xor_sync(0xffffffffu, mx, o));
        const float e0 = expf(v0 - mx), e1 = expf(v1 - mx);
        float sm = e0 + e1;
#pragma unroll
        for (int o = 16; o; o >>= 1) sm += __shfl_xor_sync(0xffffffffu, sm, o);
        const float inv = 1.0f / sm;

        reinterpret_cast<float2*>(out)[row[j] * 32 + lane] = make_float2(e0 * inv, e1 * inv);
    }
}

// ---------------------------------------------------------------------------
extern "C" void kernel_launch(void* const* d_in, const int* in_sizes, int n_in,
                              void* d_out, int out_size) {
    const float* z    = (const float*)d_in[0];
    const float* tau  = (const float*)d_in[1];
    const float* dist = (const float*)d_in[2];
    const float* encW = (const float*)d_in[3];
    const float* encb = (const float*)d_in[4];
    const float* msgW = (const float*)d_in[5];
    const float* msgb = (const float*)d_in[6];
    const float* updW = (const float*)d_in[7];
    const float* updb = (const float*)d_in[8];
    const float* outW = (const float*)d_in[9];
    const float* outb = (const float*)d_in[10];
    float* out = (float*)d_out;

    const int smem2 = 2 * CTILE * MSG * (int)sizeof(float);   // 64 KB
    cudaFuncSetAttribute(k2_agg, cudaFuncAttributeMaxDynamicSharedMemorySize, smem2);

    // zero g_S via a graph-capturable memset node
    void* sPtr = nullptr;
    cudaGetSymbolAddress(&sPtr, g_S);
    cudaMemsetAsync(sPtr, 0, MSG * sizeof(float), 0);

    k1_enc<<<NROW / 16, 256>>>(z, encW, encb, msgW, msgb);

    dim3 g2(NROW / 64, NCB);
    k2_agg<<<g2, TPB2, smem2>>>(dist);

    k3_tail<<<NROW / 32, TPB2>>>(dist, tau, updW, updb, outW, outb, out);
}

// round 12
// speedup vs baseline: 1.5106x; 1.5106x over previous
#include <cuda_runtime.h>
#include <cstdint>

#define NROW 8192
#define LATENT 128
#define HID 32
#define MSG 64
#define THRESH 1.5f

#define NCB 16                // column blocks (confirmed optimal R10)
#define COLB (NROW / NCB)     // 512 cols per CTA
#define CTILE 128             // cols per smem tile
#define NT (COLB / CTILE)     // 4 tiles
#define TPB2 512

// ---------------- device scratch (no allocation allowed) -------------------
__device__ __align__(16) float g_h[NROW * HID];          // 1 MB
__device__ __align__(16) float g_msgF[NROW * MSG];       // 2 MB row-major
__device__ __align__(16) float g_part[NCB * NROW * MSG]; // 32 MB fail-sum partials
__device__ float g_S[MSG];                               // column sums of messages

// ---------------- asm helpers -----------------------------------------------
__device__ __forceinline__ uint32_t smem_u32(const void* p) {
    uint32_t a;
    asm("{ .reg .u64 t; cvta.to.shared.u64 t, %1; cvt.u32.u64 %0, t; }" : "=r"(a) : "l"(p));
    return a;
}
#define CP_ASYNC16(sm, gp) \
    asm volatile("cp.async.cg.shared.global [%0], [%1], 16;" :: "r"(sm), "l"(gp) : "memory")
#define CP_COMMIT() asm volatile("cp.async.commit_group;" ::: "memory")
#define CP_WAIT0()  asm volatile("cp.async.wait_group 0;" ::: "memory")

// packed fp32x2 add (Blackwell): acc += v in one instruction
__device__ __forceinline__ void fadd2(uint64_t& a, uint64_t v) {
    asm("add.rn.f32x2 %0, %0, %1;" : "+l"(a) : "l"(v));
}

// ---------------- threefry / gumbel ----------------------------------------
__device__ __forceinline__ uint32_t rotl32(uint32_t x, int r) { return __funnelshift_l(x, x, r); }
__device__ __forceinline__ void threefry2x32_042(uint32_t x0, uint32_t x1,
                                                 uint32_t& o0, uint32_t& o1) {
    const uint32_t k0 = 0u, k1 = 42u, k2 = 0u ^ 42u ^ 0x1BD11BDAu;
    x0 += k0; x1 += k1;
#define TF_RND(r) { x0 += x1; x1 = rotl32(x1, r); x1 ^= x0; }
    TF_RND(13) TF_RND(15) TF_RND(26) TF_RND(6)
    x0 += k1; x1 += k2 + 1u;
    TF_RND(17) TF_RND(29) TF_RND(16) TF_RND(24)
    x0 += k2; x1 += k0 + 2u;
    TF_RND(13) TF_RND(15) TF_RND(26) TF_RND(6)
    x0 += k0; x1 += k1 + 3u;
    TF_RND(17) TF_RND(29) TF_RND(16) TF_RND(24)
    x0 += k1; x1 += k2 + 4u;
    TF_RND(13) TF_RND(15) TF_RND(26) TF_RND(6)
    x0 += k2; x1 += k0 + 5u;
#undef TF_RND
    o0 = x0; o1 = x1;
}
__device__ __forceinline__ float gumbel_at(uint32_t i) {
    uint32_t o0, o1;
    threefry2x32_042(0u, i, o0, o1);
    const uint32_t bits = o0 ^ o1;
    float u = __uint_as_float((bits >> 9) | 0x3f800000u) - 1.0f;
    u = u * (1.0f - 1e-10f) + 1e-10f;
    u = fmaxf(1e-10f, u);
    return -__logf(-__logf(u));
}

// ---------------- K1: h = relu(z@encW+b); msg = h@msgW+b; S += colsum -------
__global__ __launch_bounds__(256) void k1_enc(
    const float* __restrict__ z,
    const float* __restrict__ encW, const float* __restrict__ encb,
    const float* __restrict__ msgW, const float* __restrict__ msgb)
{
    __shared__ float  z_s[8 * LATENT];
    __shared__ float  h_s[8 * HID];
    __shared__ float2 m_s[8 * 32];

    const int t  = threadIdx.x;
    const int i0 = blockIdx.x * 8;

    reinterpret_cast<float4*>(z_s)[t] =
        reinterpret_cast<const float4*>(z + (size_t)i0 * LATENT)[t];
    __syncthreads();

    const int r = t >> 5, c = t & 31;

    // 4 independent accumulator chains
    float p0 = encb[c], p1 = 0.0f, p2 = 0.0f, p3 = 0.0f;
#pragma unroll
    for (int k = 0; k < LATENT; k += 4) {
        p0 = fmaf(z_s[r * LATENT + k + 0], encW[(k + 0) * HID + c], p0);
        p1 = fmaf(z_s[r * LATENT + k + 1], encW[(k + 1) * HID + c], p1);
        p2 = fmaf(z_s[r * LATENT + k + 2], encW[(k + 2) * HID + c], p2);
        p3 = fmaf(z_s[r * LATENT + k + 3], encW[(k + 3) * HID + c], p3);
    }
    const float a = fmaxf((p0 + p1) + (p2 + p3), 0.0f);
    h_s[r * HID + c] = a;
    g_h[(size_t)(i0 + r) * HID + c] = a;
    __syncthreads();

    float2 m = make_float2(msgb[2 * c], msgb[2 * c + 1]);
#pragma unroll
    for (int k = 0; k < HID; ++k) {
        float hk = h_s[r * HID + k];
        float2 w = reinterpret_cast<const float2*>(msgW)[k * 32 + c];
        m.x = fmaf(hk, w.x, m.x);
        m.y = fmaf(hk, w.y, m.y);
    }
    reinterpret_cast<float2*>(g_msgF)[(size_t)(i0 + r) * 32 + c] = m;
    m_s[r * 32 + c] = m;
    __syncthreads();

    if (t < MSG) {
        float s = 0.0f;
#pragma unroll
        for (int rr = 0; rr < 8; ++rr) {
            float2 mm = m_s[rr * 32 + (t >> 1)];
            s += (t & 1) ? mm.y : mm.x;
        }
        atomicAdd(&g_S[t], s);
    }
}

// ---------------- K2: fail-sum partials, 2D grid (rowblk x colblk) ----------
// EXACT R5 hot loop. CTA = 64 rows x 512 cols. 16 warps, 4 rows/warp.
__global__ __launch_bounds__(TPB2, 3) void k2_agg(const float* __restrict__ dists)
{
    extern __shared__ float msg_s[];          // 2 x 128*64 floats = 64KB

    const int tid  = threadIdx.x;
    const int wid  = tid >> 5;
    const int lane = tid & 31;
    const int rb   = blockIdx.x;              // 0..127
    const int cb   = blockIdx.y;              // 0..15
    const int row0 = rb * 64 + wid * 4;
    const int col0 = cb * COLB;

    const float* d0 = dists + (size_t)(row0 + 0) * NROW + col0 + lane * 4;
    const float* d1 = d0 + NROW;
    const float* d2 = d1 + NROW;
    const float* d3 = d2 + NROW;

    uint64_t acc[4] = {0ull, 0ull, 0ull, 0ull};   // packed f32x2 accumulators

    const uint32_t sm0 = smem_u32(msg_s);

    // prefetch tile 0 into buffer 0
    {
        const float4* src = reinterpret_cast<const float4*>(g_msgF + (size_t)col0 * MSG);
#pragma unroll
        for (int q = 0; q < 4; ++q)
            CP_ASYNC16(sm0 + (tid + q * TPB2) * 16, src + tid + q * TPB2);
        CP_COMMIT();
    }

#pragma unroll 1
    for (int t = 0; t < NT; ++t) {
        const int s = t & 1;
        CP_WAIT0();
        __syncthreads();
        if (t + 1 < NT) {
            const uint32_t dst = sm0 + ((s ^ 1) * CTILE * MSG) * 4;
            const float4* src = reinterpret_cast<const float4*>(
                g_msgF + (size_t)(col0 + (t + 1) * CTILE) * MSG);
#pragma unroll
            for (int q = 0; q < 4; ++q)
                CP_ASYNC16(dst + (tid + q * TPB2) * 16, src + tid + q * TPB2);
            CP_COMMIT();
        }

        const char* ms = reinterpret_cast<const char*>(msg_s)
                       + s * (CTILE * MSG * 4) + lane * 8;
        const int ofs = t * CTILE;

        // front-batch all 4 row loads (MLP=4), streaming (evict-first)
        const float4 dA = __ldcs(reinterpret_cast<const float4*>(d0 + ofs));
        const float4 dB = __ldcs(reinterpret_cast<const float4*>(d1 + ofs));
        const float4 dC = __ldcs(reinterpret_cast<const float4*>(d2 + ofs));
        const float4 dD = __ldcs(reinterpret_cast<const float4*>(d3 + ofs));

#define ROW_TILE(r, d4) { \
        unsigned m0 = __ballot_sync(0xffffffffu, d4.x >= THRESH);                     \
        unsigned m1 = __ballot_sync(0xffffffffu, d4.y >= THRESH);                     \
        unsigned m2 = __ballot_sync(0xffffffffu, d4.z >= THRESH);                     \
        unsigned m3 = __ballot_sync(0xffffffffu, d4.w >= THRESH);                     \
        while (m0) { int b = __ffs(m0) - 1; m0 &= m0 - 1;                             \
            fadd2(acc[r], *reinterpret_cast<const uint64_t*>(ms + 0 * 256 + b * 1024)); } \
        while (m1) { int b = __ffs(m1) - 1; m1 &= m1 - 1;                             \
            fadd2(acc[r], *reinterpret_cast<const uint64_t*>(ms + 1 * 256 + b * 1024)); } \
        while (m2) { int b = __ffs(m2) - 1; m2 &= m2 - 1;                             \
            fadd2(acc[r], *reinterpret_cast<const uint64_t*>(ms + 2 * 256 + b * 1024)); } \
        while (m3) { int b = __ffs(m3) - 1; m3 &= m3 - 1;                             \
            fadd2(acc[r], *reinterpret_cast<const uint64_t*>(ms + 3 * 256 + b * 1024)); } }

        ROW_TILE(0, dA)
        ROW_TILE(1, dB)
        ROW_TILE(2, dC)
        ROW_TILE(3, dD)
#undef ROW_TILE
    }

    uint64_t* gp = reinterpret_cast<uint64_t*>(g_part) +
                   ((size_t)cb * NROW + row0) * 32 + lane;
#pragma unroll
    for (int r = 0; r < 4; ++r) gp[r * 32] = acc[r];
}

// ---------------- K3: combine partials + gumbel + fused tail -----------------
// 256 CTAs x 512 thr; 16 warps x 2 interleaved rows (2 independent chains).
__global__ __launch_bounds__(TPB2) void k3_tail(
    const float* __restrict__ dists, const float* __restrict__ tau,
    const float* __restrict__ updW,  const float* __restrict__ updb,
    const float* __restrict__ outW,  const float* __restrict__ outb,
    float* __restrict__ out)
{
    const int wid  = threadIdx.x >> 5;
    const int lane = threadIdx.x & 31;
    const float itau = 1.0f / tau[0];

    const size_t row[2] = { (size_t)blockIdx.x * 32 + wid * 2,
                            (size_t)blockIdx.x * 32 + wid * 2 + 1 };

    const float2 Sv = reinterpret_cast<const float2*>(g_S)[lane];

    float a0[2], a1[2], h_own[2];
#pragma unroll
    for (int j = 0; j < 2; ++j) { a0[j] = Sv.x; a1[j] = Sv.y; }

    // interleaved partial combine (independent loads, MLP high)
#pragma unroll
    for (int p = 0; p < NCB; ++p) {
#pragma unroll
        for (int j = 0; j < 2; ++j) {
            const float2 pv = reinterpret_cast<const float2*>(g_part)
                [((size_t)p * NROW + row[j]) * 32 + lane];
            a0[j] -= pv.x; a1[j] -= pv.y;
        }
    }
#pragma unroll
    for (int j = 0; j < 2; ++j) {
        const float dii = dists[row[j] * NROW + row[j]];
        const float2 mi = reinterpret_cast<const float2*>(g_msgF)[row[j] * 32 + lane];
        const float sub = (dii < THRESH) ? 1.0f : 0.0f;
        a0[j] -= sub * mi.x;
        a1[j] -= sub * mi.y;
        h_own[j] = g_h[row[j] * HID + lane];
    }

    // gumbels (4 threefry evals, independent)
    float gum0[2], gum1[2];
#pragma unroll
    for (int j = 0; j < 2; ++j) {
        const uint32_t gi = (uint32_t)row[j] * 64u + 2u * lane;
        gum0[j] = gumbel_at(gi);
        gum1[j] = gumbel_at(gi + 1);
    }

    float acc2[2] = { updb[lane], updb[lane] };
#pragma unroll
    for (int k = 0; k < 32; ++k) {
        const float wA = updW[k * HID + lane];
        const float wB = updW[(32 + k) * HID + lane];
        const float wC = updW[(64 + k) * HID + lane];
#pragma unroll
        for (int j = 0; j < 2; ++j) {
            const float hk = __shfl_sync(0xffffffffu, h_own[j], k);
            const float src = (k & 1) ? a1[j] : a0[j];
            const float gA = __shfl_sync(0xffffffffu, src, k >> 1);
            const float gB = __shfl_sync(0xffffffffu, src, 16 + (k >> 1));
            acc2[j] = fmaf(hk, wA, acc2[j]);
            acc2[j] = fmaf(gA, wB, acc2[j]);
            acc2[j] = fmaf(gB, wC, acc2[j]);
        }
    }
    float h2v[2] = { fmaxf(acc2[0], 0.0f), fmaxf(acc2[1], 0.0f) };

    float2 lg[2];
#pragma unroll
    for (int j = 0; j < 2; ++j) lg[j] = make_float2(outb[2 * lane], outb[2 * lane + 1]);
#pragma unroll
    for (int k = 0; k < 32; ++k) {
        const float2 w = reinterpret_cast<const float2*>(outW)[k * 32 + lane];
#pragma unroll
        for (int j = 0; j < 2; ++j) {
            const float h2k = __shfl_sync(0xffffffffu, h2v[j], k);
            lg[j].x = fmaf(h2k, w.x, lg[j].x);
            lg[j].y = fmaf(h2k, w.y, lg[j].y);
        }
    }

#pragma unroll
    for (int j = 0; j < 2; ++j) {
        const float v0 = (lg[j].x + gum0[j]) * itau;
        const float v1 = (lg[j].y + gum1[j]) * itau;

        float mx = fmaxf(v0, v1);
#pragma unroll
        for (int o = 16; o; o >>= 1) mx = fmaxf(mx, __shfl_xor_sync(0xffffffffu, mx, o));
        const float e0 = expf(v0 - mx), e1 = expf(v1 - mx);
        float sm = e0 + e1;
#pragma unroll
        for (int o = 16; o; o >>= 1) sm += __shfl_xor_sync(0xffffffffu, sm, o);
        const float inv = 1.0f / sm;

        reinterpret_cast<float2*>(out)[row[j] * 32 + lane] = make_float2(e0 * inv, e1 * inv);
    }
}

// ---------------------------------------------------------------------------
extern "C" void kernel_launch(void* const* d_in, const int* in_sizes, int n_in,
                              void* d_out, int out_size) {
    const float* z    = (const float*)d_in[0];
    const float* tau  = (const float*)d_in[1];
    const float* dist = (const float*)d_in[2];
    const float* encW = (const float*)d_in[3];
    const float* encb = (const float*)d_in[4];
    const float* msgW = (const float*)d_in[5];
    const float* msgb = (const float*)d_in[6];
    const float* updW = (const float*)d_in[7];
    const float* updb = (const float*)d_in[8];
    const float* outW = (const float*)d_in[9];
    const float* outb = (const float*)d_in[10];
    float* out = (float*)d_out;

    const int smem2 = 2 * CTILE * MSG * (int)sizeof(float);   // 64 KB
    cudaFuncSetAttribute(k2_agg, cudaFuncAttributeMaxDynamicSharedMemorySize, smem2);

    // zero g_S via a graph-capturable memset node
    void* sPtr = nullptr;
    cudaGetSymbolAddress(&sPtr, g_S);
    cudaMemsetAsync(sPtr, 0, MSG * sizeof(float), 0);

    k1_enc<<<NROW / 8, 256>>>(z, encW, encb, msgW, msgb);

    dim3 g2(NROW / 64, NCB);
    k2_agg<<<g2, TPB2, smem2>>>(dist);

    k3_tail<<<NROW / 32, TPB2>>>(dist, tau, updW, updb, outW, outb, out);
}

// round 13
// speedup vs baseline: 1.5343x; 1.0157x over previous
#include <cuda_runtime.h>
#include <cstdint>

#define NROW 8192
#define LATENT 128
#define HID 32
#define MSG 64
#define THRESH 1.5f

#define NCB 16                // column blocks (confirmed optimal R10)
#define COLB (NROW / NCB)     // 512 cols per CTA
#define CTILE 64              // cols per smem tile (R13: halved for 4 CTAs/SM)
#define NT (COLB / CTILE)     // 8 tiles
#define TPB2 512

// ---------------- device scratch (no allocation allowed) -------------------
__device__ __align__(16) float g_h[NROW * HID];          // 1 MB
__device__ __align__(16) float g_msgF[NROW * MSG];       // 2 MB row-major
__device__ __align__(16) float g_part[NCB * NROW * MSG]; // 32 MB fail-sum partials
__device__ float g_S[MSG];                               // column sums of messages

// ---------------- asm helpers -----------------------------------------------
__device__ __forceinline__ uint32_t smem_u32(const void* p) {
    uint32_t a;
    asm("{ .reg .u64 t; cvta.to.shared.u64 t, %1; cvt.u32.u64 %0, t; }" : "=r"(a) : "l"(p));
    return a;
}
#define CP_ASYNC16(sm, gp) \
    asm volatile("cp.async.cg.shared.global [%0], [%1], 16;" :: "r"(sm), "l"(gp) : "memory")
#define CP_COMMIT() asm volatile("cp.async.commit_group;" ::: "memory")
#define CP_WAIT0()  asm volatile("cp.async.wait_group 0;" ::: "memory")

// packed fp32x2 add (Blackwell): acc += v in one instruction
__device__ __forceinline__ void fadd2(uint64_t& a, uint64_t v) {
    asm("add.rn.f32x2 %0, %0, %1;" : "+l"(a) : "l"(v));
}

// ---------------- threefry / gumbel ----------------------------------------
__device__ __forceinline__ uint32_t rotl32(uint32_t x, int r) { return __funnelshift_l(x, x, r); }
__device__ __forceinline__ void threefry2x32_042(uint32_t x0, uint32_t x1,
                                                 uint32_t& o0, uint32_t& o1) {
    const uint32_t k0 = 0u, k1 = 42u, k2 = 0u ^ 42u ^ 0x1BD11BDAu;
    x0 += k0; x1 += k1;
#define TF_RND(r) { x0 += x1; x1 = rotl32(x1, r); x1 ^= x0; }
    TF_RND(13) TF_RND(15) TF_RND(26) TF_RND(6)
    x0 += k1; x1 += k2 + 1u;
    TF_RND(17) TF_RND(29) TF_RND(16) TF_RND(24)
    x0 += k2; x1 += k0 + 2u;
    TF_RND(13) TF_RND(15) TF_RND(26) TF_RND(6)
    x0 += k0; x1 += k1 + 3u;
    TF_RND(17) TF_RND(29) TF_RND(16) TF_RND(24)
    x0 += k1; x1 += k2 + 4u;
    TF_RND(13) TF_RND(15) TF_RND(26) TF_RND(6)
    x0 += k2; x1 += k0 + 5u;
#undef TF_RND
    o0 = x0; o1 = x1;
}
__device__ __forceinline__ float gumbel_at(uint32_t i) {
    uint32_t o0, o1;
    threefry2x32_042(0u, i, o0, o1);
    const uint32_t bits = o0 ^ o1;
    float u = __uint_as_float((bits >> 9) | 0x3f800000u) - 1.0f;
    u = u * (1.0f - 1e-10f) + 1e-10f;
    u = fmaxf(1e-10f, u);
    return -__logf(-__logf(u));
}

// ---------------- K1: h = relu(z@encW+b); msg = h@msgW+b; S += colsum -------
__global__ __launch_bounds__(256) void k1_enc(
    const float* __restrict__ z,
    const float* __restrict__ encW, const float* __restrict__ encb,
    const float* __restrict__ msgW, const float* __restrict__ msgb)
{
    __shared__ float  z_s[8 * LATENT];
    __shared__ float  h_s[8 * HID];
    __shared__ float2 m_s[8 * 32];

    const int t  = threadIdx.x;
    const int i0 = blockIdx.x * 8;

    reinterpret_cast<float4*>(z_s)[t] =
        reinterpret_cast<const float4*>(z + (size_t)i0 * LATENT)[t];
    __syncthreads();

    const int r = t >> 5, c = t & 31;

    // 4 independent accumulator chains
    float p0 = encb[c], p1 = 0.0f, p2 = 0.0f, p3 = 0.0f;
#pragma unroll
    for (int k = 0; k < LATENT; k += 4) {
        p0 = fmaf(z_s[r * LATENT + k + 0], encW[(k + 0) * HID + c], p0);
        p1 = fmaf(z_s[r * LATENT + k + 1], encW[(k + 1) * HID + c], p1);
        p2 = fmaf(z_s[r * LATENT + k + 2], encW[(k + 2) * HID + c], p2);
        p3 = fmaf(z_s[r * LATENT + k + 3], encW[(k + 3) * HID + c], p3);
    }
    const float a = fmaxf((p0 + p1) + (p2 + p3), 0.0f);
    h_s[r * HID + c] = a;
    g_h[(size_t)(i0 + r) * HID + c] = a;
    __syncthreads();

    float2 m = make_float2(msgb[2 * c], msgb[2 * c + 1]);
#pragma unroll
    for (int k = 0; k < HID; ++k) {
        float hk = h_s[r * HID + k];
        float2 w = reinterpret_cast<const float2*>(msgW)[k * 32 + c];
        m.x = fmaf(hk, w.x, m.x);
        m.y = fmaf(hk, w.y, m.y);
    }
    reinterpret_cast<float2*>(g_msgF)[(size_t)(i0 + r) * 32 + c] = m;
    m_s[r * 32 + c] = m;
    __syncthreads();

    if (t < MSG) {
        float s = 0.0f;
#pragma unroll
        for (int rr = 0; rr < 8; ++rr) {
            float2 mm = m_s[rr * 32 + (t >> 1)];
            s += (t & 1) ? mm.y : mm.x;
        }
        atomicAdd(&g_S[t], s);
    }
}

// ---------------- K2: fail-sum partials, 2D grid (rowblk x colblk) ----------
// CTA = 64 rows x 512 cols. 16 warps, 4 rows/warp. Double-buffered 64-col tile
// (2 x 16KB = 32KB) -> 4 CTAs/SM = 64 warps (full occupancy).
__global__ __launch_bounds__(TPB2, 4) void k2_agg(const float* __restrict__ dists)
{
    extern __shared__ float msg_s[];          // 2 x 64*64 floats = 32KB

    const int tid  = threadIdx.x;
    const int wid  = tid >> 5;
    const int lane = tid & 31;
    const int rb   = blockIdx.x;              // 0..127
    const int cb   = blockIdx.y;              // 0..15
    const int row0 = rb * 64 + wid * 4;
    const int col0 = cb * COLB;

    // lane covers cols (2*lane, 2*lane+1) within each 64-col tile
    const float* d0 = dists + (size_t)(row0 + 0) * NROW + col0 + lane * 2;
    const float* d1 = d0 + NROW;
    const float* d2 = d1 + NROW;
    const float* d3 = d2 + NROW;

    uint64_t acc[4] = {0ull, 0ull, 0ull, 0ull};   // packed f32x2 accumulators

    const uint32_t sm0 = smem_u32(msg_s);

    // prefetch tile 0 into buffer 0 (16KB = 1024 float4, 2 per thread)
    {
        const float4* src = reinterpret_cast<const float4*>(g_msgF + (size_t)col0 * MSG);
#pragma unroll
        for (int q = 0; q < 2; ++q)
            CP_ASYNC16(sm0 + (tid + q * TPB2) * 16, src + tid + q * TPB2);
        CP_COMMIT();
    }

#pragma unroll 1
    for (int t = 0; t < NT; ++t) {
        const int s = t & 1;
        CP_WAIT0();
        __syncthreads();
        if (t + 1 < NT) {
            const uint32_t dst = sm0 + ((s ^ 1) * CTILE * MSG) * 4;
            const float4* src = reinterpret_cast<const float4*>(
                g_msgF + (size_t)(col0 + (t + 1) * CTILE) * MSG);
#pragma unroll
            for (int q = 0; q < 2; ++q)
                CP_ASYNC16(dst + (tid + q * TPB2) * 16, src + tid + q * TPB2);
            CP_COMMIT();
        }

        const char* ms = reinterpret_cast<const char*>(msg_s)
                       + s * (CTILE * MSG * 4) + lane * 8;
        const int ofs = t * CTILE;

        // front-batch all 4 row loads (MLP=4), streaming (evict-first)
        const float2 dA = __ldcs(reinterpret_cast<const float2*>(d0 + ofs));
        const float2 dB = __ldcs(reinterpret_cast<const float2*>(d1 + ofs));
        const float2 dC = __ldcs(reinterpret_cast<const float2*>(d2 + ofs));
        const float2 dD = __ldcs(reinterpret_cast<const float2*>(d3 + ofs));

        // bit b of m0 <-> col 2b (offset b*512); m1 <-> col 2b+1 (b*512+256)
#define ROW_TILE(r, d2v) { \
        unsigned m0 = __ballot_sync(0xffffffffu, d2v.x >= THRESH);                    \
        unsigned m1 = __ballot_sync(0xffffffffu, d2v.y >= THRESH);                    \
        while (m0) { int b = __ffs(m0) - 1; m0 &= m0 - 1;                             \
            fadd2(acc[r], *reinterpret_cast<const uint64_t*>(ms + b * 512)); }        \
        while (m1) { int b = __ffs(m1) - 1; m1 &= m1 - 1;                             \
            fadd2(acc[r], *reinterpret_cast<const uint64_t*>(ms + b * 512 + 256)); } }

        ROW_TILE(0, dA)
        ROW_TILE(1, dB)
        ROW_TILE(2, dC)
        ROW_TILE(3, dD)
#undef ROW_TILE
    }

    uint64_t* gp = reinterpret_cast<uint64_t*>(g_part) +
                   ((size_t)cb * NROW + row0) * 32 + lane;
#pragma unroll
    for (int r = 0; r < 4; ++r) gp[r * 32] = acc[r];
}

// ---------------- K3: combine partials + gumbel + fused tail -----------------
// 256 CTAs x 512 thr; 16 warps x 2 interleaved rows (2 independent chains).
__global__ __launch_bounds__(TPB2) void k3_tail(
    const float* __restrict__ dists, const float* __restrict__ tau,
    const float* __restrict__ updW,  const float* __restrict__ updb,
    const float* __restrict__ outW,  const float* __restrict__ outb,
    float* __restrict__ out)
{
    const int wid  = threadIdx.x >> 5;
    const int lane = threadIdx.x & 31;
    const float itau = 1.0f / tau[0];

    const size_t row[2] = { (size_t)blockIdx.x * 32 + wid * 2,
                            (size_t)blockIdx.x * 32 + wid * 2 + 1 };

    const float2 Sv = reinterpret_cast<const float2*>(g_S)[lane];

    float a0[2], a1[2], h_own[2];
#pragma unroll
    for (int j = 0; j < 2; ++j) { a0[j] = Sv.x; a1[j] = Sv.y; }

    // interleaved partial combine (independent loads, MLP high)
#pragma unroll
    for (int p = 0; p < NCB; ++p) {
#pragma unroll
        for (int j = 0; j < 2; ++j) {
            const float2 pv = reinterpret_cast<const float2*>(g_part)
                [((size_t)p * NROW + row[j]) * 32 + lane];
            a0[j] -= pv.x; a1[j] -= pv.y;
        }
    }
#pragma unroll
    for (int j = 0; j < 2; ++j) {
        const float dii = dists[row[j] * NROW + row[j]];
        const float2 mi = reinterpret_cast<const float2*>(g_msgF)[row[j] * 32 + lane];
        const float sub = (dii < THRESH) ? 1.0f : 0.0f;
        a0[j] -= sub * mi.x;
        a1[j] -= sub * mi.y;
        h_own[j] = g_h[row[j] * HID + lane];
    }

    // gumbels (4 threefry evals, independent)
    float gum0[2], gum1[2];
#pragma unroll
    for (int j = 0; j < 2; ++j) {
        const uint32_t gi = (uint32_t)row[j] * 64u + 2u * lane;
        gum0[j] = gumbel_at(gi);
        gum1[j] = gumbel_at(gi + 1);
    }

    float acc2[2] = { updb[lane], updb[lane] };
#pragma unroll
    for (int k = 0; k < 32; ++k) {
        const float wA = updW[k * HID + lane];
        const float wB = updW[(32 + k) * HID + lane];
        const float wC = updW[(64 + k) * HID + lane];
#pragma unroll
        for (int j = 0; j < 2; ++j) {
            const float hk = __shfl_sync(0xffffffffu, h_own[j], k);
            const float src = (k & 1) ? a1[j] : a0[j];
            const float gA = __shfl_sync(0xffffffffu, src, k >> 1);
            const float gB = __shfl_sync(0xffffffffu, src, 16 + (k >> 1));
            acc2[j] = fmaf(hk, wA, acc2[j]);
            acc2[j] = fmaf(gA, wB, acc2[j]);
            acc2[j] = fmaf(gB, wC, acc2[j]);
        }
    }
    float h2v[2] = { fmaxf(acc2[0], 0.0f), fmaxf(acc2[1], 0.0f) };

    float2 lg[2];
#pragma unroll
    for (int j = 0; j < 2; ++j) lg[j] = make_float2(outb[2 * lane], outb[2 * lane + 1]);
#pragma unroll
    for (int k = 0; k < 32; ++k) {
        const float2 w = reinterpret_cast<const float2*>(outW)[k * 32 + lane];
#pragma unroll
        for (int j = 0; j < 2; ++j) {
            const float h2k = __shfl_sync(0xffffffffu, h2v[j], k);
            lg[j].x = fmaf(h2k, w.x, lg[j].x);
            lg[j].y = fmaf(h2k, w.y, lg[j].y);
        }
    }

#pragma unroll
    for (int j = 0; j < 2; ++j) {
        const float v0 = (lg[j].x + gum0[j]) * itau;
        const float v1 = (lg[j].y + gum1[j]) * itau;

        float mx = fmaxf(v0, v1);
#pragma unroll
        for (int o = 16; o; o >>= 1) mx = fmaxf(mx, __shfl_xor_sync(0xffffffffu, mx, o));
        const float e0 = expf(v0 - mx), e1 = expf(v1 - mx);
        float sm = e0 + e1;
#pragma unroll
        for (int o = 16; o; o >>= 1) sm += __shfl_xor_sync(0xffffffffu, sm, o);
        const float inv = 1.0f / sm;

        reinterpret_cast<float2*>(out)[row[j] * 32 + lane] = make_float2(e0 * inv, e1 * inv);
    }
}

// ---------------------------------------------------------------------------
extern "C" void kernel_launch(void* const* d_in, const int* in_sizes, int n_in,
                              void* d_out, int out_size) {
    const float* z    = (const float*)d_in[0];
    const float* tau  = (const float*)d_in[1];
    const float* dist = (const float*)d_in[2];
    const float* encW = (const float*)d_in[3];
    const float* encb = (const float*)d_in[4];
    const float* msgW = (const float*)d_in[5];
    const float* msgb = (const float*)d_in[6];
    const float* updW = (const float*)d_in[7];
    const float* updb = (const float*)d_in[8];
    const float* outW = (const float*)d_in[9];
    const float* outb = (const float*)d_in[10];
    float* out = (float*)d_out;

    const int smem2 = 2 * CTILE * MSG * (int)sizeof(float);   // 32 KB
    cudaFuncSetAttribute(k2_agg, cudaFuncAttributeMaxDynamicSharedMemorySize, smem2);

    // zero g_S via a graph-capturable memset node
    void* sPtr = nullptr;
    cudaGetSymbolAddress(&sPtr, g_S);
    cudaMemsetAsync(sPtr, 0, MSG * sizeof(float), 0);

    k1_enc<<<NROW / 8, 256>>>(z, encW, encb, msgW, msgb);

    dim3 g2(NROW / 64, NCB);
    k2_agg<<<g2, TPB2, smem2>>>(dist);

    k3_tail<<<NROW / 32, TPB2>>>(dist, tau, updW, updb, outW, outb, out);
}